// round 15
// baseline (speedup 1.0000x reference)
#include <cuda_runtime.h>
#include <math.h>

typedef unsigned long long u64;
#define DEV __device__ __forceinline__

// ---- packed f32x2 helpers (sm_103a) ----
DEV u64 ffma2(u64 a, u64 b, u64 c) { u64 d; asm("fma.rn.f32x2 %0,%1,%2,%3;" : "=l"(d) : "l"(a), "l"(b), "l"(c)); return d; }
DEV u64 fmul2(u64 a, u64 b) { u64 d; asm("mul.rn.f32x2 %0,%1,%2;" : "=l"(d) : "l"(a), "l"(b)); return d; }
DEV u64 pk2(float x, float y) { u64 d; asm("mov.b64 %0,{%1,%2};" : "=l"(d) : "f"(x), "f"(y)); return d; }
DEV float2 upk(u64 v) { float2 r; asm("mov.b64 {%0,%1},%2;" : "=f"(r.x), "=f"(r.y) : "l"(v)); return r; }
DEV float hadd(u64 v) { float2 f = upk(v); return f.x + f.y; }
DEV u64 ldsh(const float2& p) { return *reinterpret_cast<const u64*>(&p); }
DEV float gelu_exact(float v) { return 0.5f * v * (1.0f + erff(v * 0.70710678118654752f)); }

// ---- fixed problem shape (B,T,H,W)=(2,15,192,192), C=P=16 ----
constexpr int T_   = 15;
constexpr int C_   = 16;
constexpr int KP   = 8;           // pairs of 16
constexpr int HW_  = 192 * 192;   // 36864
constexpr int B_   = 2;
constexpr int NSEQ = B_ * HW_;    // 73728 = 288*256
constexpr float EPS_ = 1e-5f;
constexpr float INV2PI = 0.15915494309189535f;

__global__ void __launch_bounds__(256, 1) ssm_kernel(
    const float* __restrict__ x,
    const float* __restrict__ w_in, const float* __restrict__ b_in,
    const float* __restrict__ ag,   const float* __restrict__ ab,
    const float* __restrict__ Lre,  const float* __restrict__ Lim,
    const float* __restrict__ Bre,  const float* __restrict__ Bim,
    const float* __restrict__ Cre,  const float* __restrict__ Cim,
    const float* __restrict__ Dv,   const float* __restrict__ lstep,
    const float* __restrict__ ffg,  const float* __restrict__ ffb,
    const float* __restrict__ We,   const float* __restrict__ Wd,
    const float* __restrict__ og,   const float* __restrict__ ob,
    const float* __restrict__ Wo,   const float* __restrict__ bo,
    float* __restrict__ out)
{
    // scan / mixing constants, packed as p-pairs
    __shared__ float2 sLr[KP], sLi[KP], sNli[KP];
    __shared__ float2 sP1r[KP], sP1i[KP], sNP1i[KP], sP2r[KP], sP2i[KP], sNP2i[KP], sQ3r[KP], sQ3i[KP];
    __shared__ float2 sCr[C_][KP], sNCi[C_][KP];
    __shared__ float2 sWe[2 * C_][KP], sWd[C_][KP], sWo[C_][KP];
    __shared__ float sWc[C_], sBc[C_], sG1[C_], sB1[C_], sD[C_];
    __shared__ float sFfg[C_], sFfb[C_], sOg[C_], sOb[C_], sBo[C_];
    __shared__ float sMask[C_];
    __shared__ float sVarA, sVarB2, sVarC;

    const int tid = threadIdx.x;

    // ---- cooperative weight loads (raw weights used as-is) ----
    ((float2*)sWe)[tid] = ((const float2*)We)[tid];           // 256 float2 exactly
    if (tid < 128) {
        ((float2*)sWd)[tid] = ((const float2*)Wd)[tid];
        ((float2*)sWo)[tid] = ((const float2*)Wo)[tid];
    }

    // ---- per-block precompute (tiny: P=16 threads) ----
    if (tid < 16) {
        const int p = tid;
        float mw = 0.f, mb = 0.f;
        #pragma unroll
        for (int c = 0; c < C_; c++) { mw += w_in[c]; mb += b_in[c]; }
        mw *= (1.f / C_); mb *= (1.f / C_);

        float step = expf(lstep[p]);
        float ar = Lre[p], ai = Lim[p];
        float ea = expf(ar * step);
        float lr = ea * cosf(ai * step);
        float li = ea * sinf(ai * step);
        ((float*)sLr)[p] = lr; ((float*)sLi)[p] = li; ((float*)sNli)[p] = -li;

        // coef = (Lam_bar - 1)/Lam
        float inv = 1.f / (ar * ar + ai * ai);
        float cr = ((lr - 1.f) * ar + li * ai) * inv;
        float ci = (li * ar - (lr - 1.f) * ai) * inv;

        float p1r = 0.f, p1i = 0.f, p2r = 0.f, p2i = 0.f, p3r = 0.f, p3i = 0.f;
        #pragma unroll
        for (int c = 0; c < C_; c++) {
            float br = Bre[p * C_ + c], bi = Bim[p * C_ + c];
            float rr = cr * br - ci * bi;
            float ri = cr * bi + ci * br;
            float gg = ag[c];
            float wc = (w_in[c] - mw) * gg;
            float bc = (b_in[c] - mb) * gg;
            float be = ab[c];
            p1r = fmaf(wc, rr, p1r); p1i = fmaf(wc, ri, p1i);
            p2r = fmaf(bc, rr, p2r); p2i = fmaf(bc, ri, p2i);
            p3r = fmaf(be, rr, p3r); p3i = fmaf(be, ri, p3i);
        }
        ((float*)sP1r)[p] = p1r; ((float*)sP1i)[p] = p1i; ((float*)sNP1i)[p] = -p1i;
        ((float*)sP2r)[p] = p2r; ((float*)sP2i)[p] = p2i; ((float*)sNP2i)[p] = -p2i;

        // S = sum_{j=0..T-1} Lam_bar^j  ;  Q3 = P3 * S
        float srr = 0.f, sii = 0.f, cR = 1.f, cI = 0.f;
        #pragma unroll
        for (int j = 0; j < T_; j++) {
            srr += cR; sii += cI;
            float nR = cR * lr - cI * li;
            cI = cR * li + cI * lr;
            cR = nR;
        }
        ((float*)sQ3r)[p] = p3r * srr - p3i * sii;
        ((float*)sQ3i)[p] = p3r * sii + p3i * srr;

        sMask[p] = (step * fabsf(ai) * INV2PI) < 0.25f ? 1.f : 0.f;

        // per-channel vectors (C=P=16)
        sWc[p] = w_in[p] - mw;  sBc[p] = b_in[p] - mb;
        sG1[p] = ag[p];  sB1[p] = ab[p];  sD[p] = Dv[p];
        sFfg[p] = ffg[p]; sFfb[p] = ffb[p];
        sOg[p] = og[p];  sOb[p] = ob[p];  sBo[p] = bo[p];

        if (p == 0) {
            float A = 0.f, Bs = 0.f, Cs = 0.f;
            #pragma unroll
            for (int c = 0; c < C_; c++) {
                float wc2 = w_in[c] - mw, bc2 = b_in[c] - mb;
                A += wc2 * wc2; Bs += wc2 * bc2; Cs += bc2 * bc2;
            }
            sVarA = A * (1.f / C_); sVarB2 = 2.f * Bs * (1.f / C_); sVarC = Cs * (1.f / C_);
        }
    }
    __syncthreads();

    // ---- bandlimit-masked C matrices (need sMask) ----
    {
        int c = tid >> 4, p = tid & 15;
        float m = sMask[p];
        ((float*)sCr)[tid]  =  Cre[tid] * m;
        ((float*)sNCi)[tid] = -Cim[tid] * m;
    }
    __syncthreads();

    const int n = blockIdx.x * 256 + tid;
    if (n >= NSEQ) return;
    const int b  = n / HW_;
    const int hw = n - b * HW_;
    const float* xp = x + (size_t)b * (T_ * HW_) + hw;

    // prefetch all T inputs (MLP=15, coalesced)
    float xv[T_];
    #pragma unroll
    for (int t = 0; t < T_; t++) xv[t] = __ldg(xp + t * HW_);

    const float varA = sVarA, varB2 = sVarB2, varC = sVarC;

    // scan constants -> registers
    u64 lrk[KP], lik[KP], nlik[KP];
    #pragma unroll
    for (int k = 0; k < KP; k++) { lrk[k] = ldsh(sLr[k]); lik[k] = ldsh(sLi[k]); nlik[k] = ldsh(sNli[k]); }

    // Horner accumulators: W1 over s1 = r*x, W2 over s0 = r (complex, p-paired)
    u64 W1r[KP], W1i[KP], W2r[KP], W2i[KP];
    #pragma unroll
    for (int k = 0; k < KP; k++) { W1r[k] = 0ull; W1i[k] = 0ull; W2r[k] = 0ull; W2i[k] = 0ull; }

    float rl = 0.f;
    #pragma unroll
    for (int t = 0; t < T_; t++) {
        float xt = xv[t];
        float var = fmaf(xt, fmaf(xt, varA, varB2), varC);
        float r = rsqrtf(var + EPS_);
        if (t == T_ - 1) rl = r;
        float s1 = r * xt;
        u64 s1v = pk2(s1, s1);
        u64 s0v = pk2(r, r);
        #pragma unroll
        for (int k = 0; k < KP; k++) {
            // W = W*Lam_bar + s
            u64 a1 = ffma2(lrk[k], W1r[k], ffma2(nlik[k], W1i[k], s1v));
            u64 b1 = ffma2(lik[k], W1r[k], fmul2(lrk[k], W1i[k]));
            W1r[k] = a1; W1i[k] = b1;
            u64 a2 = ffma2(lrk[k], W2r[k], ffma2(nlik[k], W2i[k], s0v));
            u64 b2 = ffma2(lik[k], W2r[k], fmul2(lrk[k], W2i[k]));
            W2r[k] = a2; W2i[k] = b2;
        }
    }

    // x_final = P1*W1 + P2*W2 + Q3  (complex)
    u64 xfr[KP], xfi[KP];
    #pragma unroll
    for (int k = 0; k < KP; k++) {
        xfr[k] = ffma2(ldsh(sP1r[k]), W1r[k],
                 ffma2(ldsh(sNP1i[k]), W1i[k],
                 ffma2(ldsh(sP2r[k]), W2r[k],
                 ffma2(ldsh(sNP2i[k]), W2i[k], ldsh(sQ3r[k])))));
        xfi[k] = ffma2(ldsh(sP1r[k]), W1i[k],
                 ffma2(ldsh(sP1i[k]), W1r[k],
                 ffma2(ldsh(sP2r[k]), W2i[k],
                 ffma2(ldsh(sP2i[k]), W2r[k], ldsh(sQ3i[k])))));
    }

    // ---- t = T-1 only from here on ----
    const float xl = xv[T_ - 1];
    float z[C_];
    #pragma unroll
    for (int c = 0; c < C_; c++) {
        u64 acc = 0ull;
        #pragma unroll
        for (int k = 0; k < KP; k++)
            acc = ffma2(xfr[k], ldsh(sCr[c][k]), ffma2(xfi[k], ldsh(sNCi[c][k]), acc));
        float yc = hadd(acc);
        float fx = fmaf(fmaf(xl, sWc[c], sBc[c]) * rl, sG1[c], sB1[c]);
        yc = fmaf(fx, sD[c], yc);
        z[c] = gelu_exact(yc) + fx;
    }

    // LN(z) -> fx2
    float mu = 0.f;
    #pragma unroll
    for (int c = 0; c < C_; c++) mu += z[c];
    mu *= (1.f / C_);
    float vv = 0.f;
    #pragma unroll
    for (int c = 0; c < C_; c++) { float d = z[c] - mu; vv = fmaf(d, d, vv); }
    float rs = rsqrtf(vv * (1.f / C_) + EPS_);
    float fx2s[C_];
    #pragma unroll
    for (int c = 0; c < C_; c++) fx2s[c] = fmaf((z[c] - mu) * rs, sFfg[c], sFfb[c]);

    u64 f2p[KP];
    #pragma unroll
    for (int k = 0; k < KP; k++) f2p[k] = pk2(fx2s[2 * k], fx2s[2 * k + 1]);

    // enc = fx2 @ We^T ; h = a * gelu(g)
    float av[C_];
    #pragma unroll
    for (int j = 0; j < C_; j++) {
        u64 acc = 0ull;
        #pragma unroll
        for (int k = 0; k < KP; k++) acc = ffma2(f2p[k], ldsh(sWe[j][k]), acc);
        av[j] = hadd(acc);
    }
    float hv[C_];
    #pragma unroll
    for (int j = 0; j < C_; j++) {
        u64 acc = 0ull;
        #pragma unroll
        for (int k = 0; k < KP; k++) acc = ffma2(f2p[k], ldsh(sWe[C_ + j][k]), acc);
        hv[j] = av[j] * gelu_exact(hadd(acc));
    }
    u64 hp[KP];
    #pragma unroll
    for (int k = 0; k < KP; k++) hp[k] = pk2(hv[2 * k], hv[2 * k + 1]);

    // z2 = h @ Wd^T + fx2
    float z2[C_];
    #pragma unroll
    for (int c = 0; c < C_; c++) {
        u64 acc = 0ull;
        #pragma unroll
        for (int k = 0; k < KP; k++) acc = ffma2(hp[k], ldsh(sWd[c][k]), acc);
        z2[c] = hadd(acc) + fx2s[c];
    }

    // LN(z2) -> v ; out = v @ Wo^T + b_out
    float mu2 = 0.f;
    #pragma unroll
    for (int c = 0; c < C_; c++) mu2 += z2[c];
    mu2 *= (1.f / C_);
    float vv2 = 0.f;
    #pragma unroll
    for (int c = 0; c < C_; c++) { float d = z2[c] - mu2; vv2 = fmaf(d, d, vv2); }
    float rs2 = rsqrtf(vv2 * (1.f / C_) + EPS_);
    u64 vp[KP];
    #pragma unroll
    for (int k = 0; k < KP; k++) {
        float v0 = fmaf((z2[2 * k]     - mu2) * rs2, sOg[2 * k],     sOb[2 * k]);
        float v1 = fmaf((z2[2 * k + 1] - mu2) * rs2, sOg[2 * k + 1], sOb[2 * k + 1]);
        vp[k] = pk2(v0, v1);
    }

    float* op = out + (size_t)b * (C_ * HW_) + hw;
    #pragma unroll
    for (int c = 0; c < C_; c++) {
        u64 acc = 0ull;
        #pragma unroll
        for (int k = 0; k < KP; k++) acc = ffma2(vp[k], ldsh(sWo[c][k]), acc);
        op[c * HW_] = hadd(acc) + sBo[c];
    }
}

extern "C" void kernel_launch(void* const* d_in, const int* in_sizes, int n_in,
                              void* d_out, int out_size)
{
    const float* x     = (const float*)d_in[0];
    const float* w_in  = (const float*)d_in[1];
    const float* b_in  = (const float*)d_in[2];
    const float* ag    = (const float*)d_in[3];
    const float* ab    = (const float*)d_in[4];
    const float* Lre   = (const float*)d_in[5];
    const float* Lim   = (const float*)d_in[6];
    const float* Bre   = (const float*)d_in[7];
    const float* Bim   = (const float*)d_in[8];
    const float* Cre   = (const float*)d_in[9];
    const float* Cim   = (const float*)d_in[10];
    const float* Dv    = (const float*)d_in[11];
    const float* lstep = (const float*)d_in[12];
    const float* ffg   = (const float*)d_in[13];
    const float* ffb   = (const float*)d_in[14];
    const float* We    = (const float*)d_in[15];
    const float* Wd    = (const float*)d_in[16];
    const float* og    = (const float*)d_in[17];
    const float* ob    = (const float*)d_in[18];
    const float* Wo    = (const float*)d_in[19];
    const float* bo    = (const float*)d_in[20];

    ssm_kernel<<<NSEQ / 256, 256>>>(x, w_in, b_in, ag, ab, Lre, Lim, Bre, Bim,
                                    Cre, Cim, Dv, lstep, ffg, ffb, We, Wd,
                                    og, ob, Wo, bo, (float*)d_out);
}

// round 16
// speedup vs baseline: 1.2137x; 1.2137x over previous
#include <cuda_runtime.h>
#include <math.h>

typedef unsigned long long u64;
#define DEV __device__ __forceinline__

// ---- packed f32x2 helpers (sm_103a) ----
DEV u64 ffma2(u64 a, u64 b, u64 c) { u64 d; asm("fma.rn.f32x2 %0,%1,%2,%3;" : "=l"(d) : "l"(a), "l"(b), "l"(c)); return d; }
DEV u64 pk2(float x, float y) { u64 d; asm("mov.b64 %0,{%1,%2};" : "=l"(d) : "f"(x), "f"(y)); return d; }
DEV float2 upk(u64 v) { float2 r; asm("mov.b64 {%0,%1},%2;" : "=f"(r.x), "=f"(r.y) : "l"(v)); return r; }
DEV float hadd(u64 v) { float2 f = upk(v); return f.x + f.y; }
DEV u64 ldsh(const float2& p) { return *reinterpret_cast<const u64*>(&p); }
DEV float gelu_exact(float v) { return 0.5f * v * (1.0f + erff(v * 0.70710678118654752f)); }

// ---- fixed problem shape (B,T,H,W)=(2,15,192,192), C=P=16 ----
constexpr int T_   = 15;
constexpr int C_   = 16;
constexpr int KP   = 8;           // pairs of 16
constexpr int HW_  = 192 * 192;   // 36864
constexpr int B_   = 2;
constexpr int NSEQ = B_ * HW_;    // 73728 = 288*256
constexpr float EPS_ = 1e-5f;
constexpr float INV2PI = 0.15915494309189535f;

__global__ void __launch_bounds__(256, 2) ssm_kernel(
    const float* __restrict__ x,
    const float* __restrict__ w_in, const float* __restrict__ b_in,
    const float* __restrict__ ag,   const float* __restrict__ ab,
    const float* __restrict__ Lre,  const float* __restrict__ Lim,
    const float* __restrict__ Bre,  const float* __restrict__ Bim,
    const float* __restrict__ Cre,  const float* __restrict__ Cim,
    const float* __restrict__ Dv,   const float* __restrict__ lstep,
    const float* __restrict__ ffg,  const float* __restrict__ ffb,
    const float* __restrict__ We,   const float* __restrict__ Wd,
    const float* __restrict__ og,   const float* __restrict__ ob,
    const float* __restrict__ Wo,   const float* __restrict__ bo,
    float* __restrict__ out)
{
    // Lambda_bar^j table: (j,k) -> {Lr[2k], Lr[2k+1], Li[2k], Li[2k+1]}
    __shared__ float4 sLj[T_][KP];
    // combine constants (used once)
    __shared__ float2 sP1r[KP], sP1i[KP], sNP1i[KP], sP2r[KP], sP2i[KP], sNP2i[KP], sQ3r[KP], sQ3i[KP];
    // C mixing: (c,k) -> {Cr[2k], Cr[2k+1], -Ci[2k], -Ci[2k+1]} (bandlimit-masked)
    __shared__ float4 sCt[C_][KP];
    // weights as float4 rows
    __shared__ float4 sWe4[2 * C_][4], sWd4[C_][4], sWo4[C_][4];
    __shared__ float sWc[C_], sBc[C_], sG1[C_], sB1[C_], sD[C_];
    __shared__ float sFfg[C_], sFfb[C_], sOg[C_], sOb[C_], sBo[C_];
    __shared__ float sMask[C_];
    __shared__ float sVarA, sVarB2, sVarC;

    const int tid = threadIdx.x;

    // ---- cooperative weight loads ----
    if (tid < 128)      ((float4*)sWe4)[tid]       = ((const float4*)We)[tid];
    else if (tid < 192) ((float4*)sWd4)[tid - 128] = ((const float4*)Wd)[tid - 128];
    else                ((float4*)sWo4)[tid - 192] = ((const float4*)Wo)[tid - 192];

    // ---- per-block precompute (P=16 threads) ----
    if (tid < 16) {
        const int p = tid;
        float mw = 0.f, mb = 0.f;
        #pragma unroll
        for (int c = 0; c < C_; c++) { mw += w_in[c]; mb += b_in[c]; }
        mw *= (1.f / C_); mb *= (1.f / C_);

        float step = expf(lstep[p]);
        float ar = Lre[p], ai = Lim[p];
        float ea = expf(ar * step);
        float lr = ea * cosf(ai * step);
        float li = ea * sinf(ai * step);

        // coef = (Lam_bar - 1)/Lam
        float inv = 1.f / (ar * ar + ai * ai);
        float cr = ((lr - 1.f) * ar + li * ai) * inv;
        float ci = (li * ar - (lr - 1.f) * ai) * inv;

        float p1r = 0.f, p1i = 0.f, p2r = 0.f, p2i = 0.f, p3r = 0.f, p3i = 0.f;
        #pragma unroll
        for (int c = 0; c < C_; c++) {
            float br = Bre[p * C_ + c], bi = Bim[p * C_ + c];
            float rr = cr * br - ci * bi;
            float ri = cr * bi + ci * br;
            float gg = ag[c];
            float wc = (w_in[c] - mw) * gg;
            float bc = (b_in[c] - mb) * gg;
            float be = ab[c];
            p1r = fmaf(wc, rr, p1r); p1i = fmaf(wc, ri, p1i);
            p2r = fmaf(bc, rr, p2r); p2i = fmaf(bc, ri, p2i);
            p3r = fmaf(be, rr, p3r); p3i = fmaf(be, ri, p3i);
        }
        ((float*)sP1r)[p] = p1r; ((float*)sP1i)[p] = p1i; ((float*)sNP1i)[p] = -p1i;
        ((float*)sP2r)[p] = p2r; ((float*)sP2i)[p] = p2i; ((float*)sNP2i)[p] = -p2i;

        // Lambda_bar^j table (j=0..T-1) + S = sum Lam_bar^j
        const int base = ((p >> 1) << 2) + (p & 1);   // k*4 + half
        float srr = 0.f, sii = 0.f, cR = 1.f, cI = 0.f;
        #pragma unroll
        for (int j = 0; j < T_; j++) {
            ((float*)sLj)[j * 32 + base]     = cR;
            ((float*)sLj)[j * 32 + base + 2] = cI;
            srr += cR; sii += cI;
            float nR = cR * lr - cI * li;
            cI = cR * li + cI * lr;
            cR = nR;
        }
        ((float*)sQ3r)[p] = p3r * srr - p3i * sii;
        ((float*)sQ3i)[p] = p3r * sii + p3i * srr;

        sMask[p] = (step * fabsf(ai) * INV2PI) < 0.25f ? 1.f : 0.f;

        sWc[p] = w_in[p] - mw;  sBc[p] = b_in[p] - mb;
        sG1[p] = ag[p];  sB1[p] = ab[p];  sD[p] = Dv[p];
        sFfg[p] = ffg[p]; sFfb[p] = ffb[p];
        sOg[p] = og[p];  sOb[p] = ob[p];  sBo[p] = bo[p];

        if (p == 0) {
            float A = 0.f, Bs = 0.f, Cs = 0.f;
            #pragma unroll
            for (int c = 0; c < C_; c++) {
                float wc2 = w_in[c] - mw, bc2 = b_in[c] - mb;
                A += wc2 * wc2; Bs += wc2 * bc2; Cs += bc2 * bc2;
            }
            sVarA = A * (1.f / C_); sVarB2 = 2.f * Bs * (1.f / C_); sVarC = Cs * (1.f / C_);
        }
    }
    __syncthreads();

    // ---- bandlimit-masked C table (needs sMask) ----
    {
        int p = tid & 15;
        float m = sMask[p];
        int idx = ((tid >> 4) << 5) + ((p >> 1) << 2) + (p & 1);
        ((float*)sCt)[idx]     =  Cre[tid] * m;
        ((float*)sCt)[idx + 2] = -Cim[tid] * m;
    }
    __syncthreads();

    const int n = blockIdx.x * 256 + tid;
    const int b  = n / HW_;
    const int hw = n - b * HW_;
    const float* xp = x + (size_t)b * (T_ * HW_) + hw;

    // prefetch all T inputs (coalesced, MLP=15)
    float xv[T_];
    #pragma unroll
    for (int t = 0; t < T_; t++) xv[t] = __ldg(xp + t * HW_);

    const float varA = sVarA, varB2 = sVarB2, varC = sVarC;

    // Direct power-sum accumulators: W1 = sum s1_t*Lam^(T-1-t), W2 = sum s0_t*Lam^(T-1-t)
    u64 W1r[KP], W1i[KP], W2r[KP], W2i[KP];
    #pragma unroll
    for (int k = 0; k < KP; k++) { W1r[k] = 0ull; W1i[k] = 0ull; W2r[k] = 0ull; W2i[k] = 0ull; }

    float rl = 0.f;
    #pragma unroll
    for (int t = 0; t < T_; t++) {
        const int j = T_ - 1 - t;
        float xt = xv[t];
        float var = fmaf(xt, fmaf(xt, varA, varB2), varC);
        float r = rsqrtf(var + EPS_);
        if (t == T_ - 1) rl = r;
        float s1 = r * xt;
        u64 s1v = pk2(s1, s1);
        u64 s0v = pk2(r, r);
        #pragma unroll
        for (int k = 0; k < KP; k++) {
            float4 L = sLj[j][k];
            u64 ljr = pk2(L.x, L.y);
            u64 lji = pk2(L.z, L.w);
            W1r[k] = ffma2(s1v, ljr, W1r[k]);
            W1i[k] = ffma2(s1v, lji, W1i[k]);
            W2r[k] = ffma2(s0v, ljr, W2r[k]);
            W2i[k] = ffma2(s0v, lji, W2i[k]);
        }
    }

    // x_final = P1*W1 + P2*W2 + Q3  (complex)
    u64 xfr[KP], xfi[KP];
    #pragma unroll
    for (int k = 0; k < KP; k++) {
        xfr[k] = ffma2(ldsh(sP1r[k]), W1r[k],
                 ffma2(ldsh(sNP1i[k]), W1i[k],
                 ffma2(ldsh(sP2r[k]), W2r[k],
                 ffma2(ldsh(sNP2i[k]), W2i[k], ldsh(sQ3r[k])))));
        xfi[k] = ffma2(ldsh(sP1r[k]), W1i[k],
                 ffma2(ldsh(sP1i[k]), W1r[k],
                 ffma2(ldsh(sP2r[k]), W2i[k],
                 ffma2(ldsh(sP2i[k]), W2r[k], ldsh(sQ3i[k])))));
    }

    // ---- t = T-1 only from here on ----
    const float xl = xv[T_ - 1];
    float z[C_];
    #pragma unroll
    for (int c = 0; c < C_; c++) {
        u64 acc = 0ull;
        #pragma unroll
        for (int k = 0; k < KP; k++) {
            float4 Ct = sCt[c][k];
            acc = ffma2(xfr[k], pk2(Ct.x, Ct.y), ffma2(xfi[k], pk2(Ct.z, Ct.w), acc));
        }
        float yc = hadd(acc);
        float fx = fmaf(fmaf(xl, sWc[c], sBc[c]) * rl, sG1[c], sB1[c]);
        yc = fmaf(fx, sD[c], yc);
        z[c] = gelu_exact(yc) + fx;
    }

    // LN(z) -> fx2
    float mu = 0.f;
    #pragma unroll
    for (int c = 0; c < C_; c++) mu += z[c];
    mu *= (1.f / C_);
    float vv = 0.f;
    #pragma unroll
    for (int c = 0; c < C_; c++) { float d = z[c] - mu; vv = fmaf(d, d, vv); }
    float rs = rsqrtf(vv * (1.f / C_) + EPS_);
    float fx2s[C_];
    #pragma unroll
    for (int c = 0; c < C_; c++) fx2s[c] = fmaf((z[c] - mu) * rs, sFfg[c], sFfb[c]);

    u64 f2p[KP];
    #pragma unroll
    for (int k = 0; k < KP; k++) f2p[k] = pk2(fx2s[2 * k], fx2s[2 * k + 1]);

    // enc = fx2 @ We^T ; h = a * gelu(g)
    float av[C_];
    #pragma unroll
    for (int j = 0; j < C_; j++) {
        u64 acc = 0ull;
        #pragma unroll
        for (int q = 0; q < 4; q++) {
            float4 w = sWe4[j][q];
            acc = ffma2(f2p[2 * q],     pk2(w.x, w.y), acc);
            acc = ffma2(f2p[2 * q + 1], pk2(w.z, w.w), acc);
        }
        av[j] = hadd(acc);
    }
    float hv[C_];
    #pragma unroll
    for (int j = 0; j < C_; j++) {
        u64 acc = 0ull;
        #pragma unroll
        for (int q = 0; q < 4; q++) {
            float4 w = sWe4[C_ + j][q];
            acc = ffma2(f2p[2 * q],     pk2(w.x, w.y), acc);
            acc = ffma2(f2p[2 * q + 1], pk2(w.z, w.w), acc);
        }
        hv[j] = av[j] * gelu_exact(hadd(acc));
    }
    u64 hp[KP];
    #pragma unroll
    for (int k = 0; k < KP; k++) hp[k] = pk2(hv[2 * k], hv[2 * k + 1]);

    // z2 = h @ Wd^T + fx2
    float z2[C_];
    #pragma unroll
    for (int c = 0; c < C_; c++) {
        u64 acc = 0ull;
        #pragma unroll
        for (int q = 0; q < 4; q++) {
            float4 w = sWd4[c][q];
            acc = ffma2(hp[2 * q],     pk2(w.x, w.y), acc);
            acc = ffma2(hp[2 * q + 1], pk2(w.z, w.w), acc);
        }
        z2[c] = hadd(acc) + fx2s[c];
    }

    // LN(z2) -> v ; out = v @ Wo^T + b_out
    float mu2 = 0.f;
    #pragma unroll
    for (int c = 0; c < C_; c++) mu2 += z2[c];
    mu2 *= (1.f / C_);
    float vv2 = 0.f;
    #pragma unroll
    for (int c = 0; c < C_; c++) { float d = z2[c] - mu2; vv2 = fmaf(d, d, vv2); }
    float rs2 = rsqrtf(vv2 * (1.f / C_) + EPS_);
    u64 vp[KP];
    #pragma unroll
    for (int k = 0; k < KP; k++) {
        float v0 = fmaf((z2[2 * k]     - mu2) * rs2, sOg[2 * k],     sOb[2 * k]);
        float v1 = fmaf((z2[2 * k + 1] - mu2) * rs2, sOg[2 * k + 1], sOb[2 * k + 1]);
        vp[k] = pk2(v0, v1);
    }

    float* op = out + (size_t)b * (C_ * HW_) + hw;
    #pragma unroll
    for (int c = 0; c < C_; c++) {
        u64 acc = 0ull;
        #pragma unroll
        for (int q = 0; q < 4; q++) {
            float4 w = sWo4[c][q];
            acc = ffma2(vp[2 * q],     pk2(w.x, w.y), acc);
            acc = ffma2(vp[2 * q + 1], pk2(w.z, w.w), acc);
        }
        op[c * HW_] = hadd(acc) + sBo[c];
    }
}

extern "C" void kernel_launch(void* const* d_in, const int* in_sizes, int n_in,
                              void* d_out, int out_size)
{
    const float* x     = (const float*)d_in[0];
    const float* w_in  = (const float*)d_in[1];
    const float* b_in  = (const float*)d_in[2];
    const float* ag    = (const float*)d_in[3];
    const float* ab    = (const float*)d_in[4];
    const float* Lre   = (const float*)d_in[5];
    const float* Lim   = (const float*)d_in[6];
    const float* Bre   = (const float*)d_in[7];
    const float* Bim   = (const float*)d_in[8];
    const float* Cre   = (const float*)d_in[9];
    const float* Cim   = (const float*)d_in[10];
    const float* Dv    = (const float*)d_in[11];
    const float* lstep = (const float*)d_in[12];
    const float* ffg   = (const float*)d_in[13];
    const float* ffb   = (const float*)d_in[14];
    const float* We    = (const float*)d_in[15];
    const float* Wd    = (const float*)d_in[16];
    const float* og    = (const float*)d_in[17];
    const float* ob    = (const float*)d_in[18];
    const float* Wo    = (const float*)d_in[19];
    const float* bo    = (const float*)d_in[20];

    ssm_kernel<<<NSEQ / 256, 256>>>(x, w_in, b_in, ag, ab, Lre, Lim, Bre, Bim,
                                    Cre, Cim, Dv, lstep, ffg, ffb, We, Wd,
                                    og, ob, Wo, bo, (float*)d_out);
}